// round 11
// baseline (speedup 1.0000x reference)
#include <cuda_runtime.h>
#include <cuda_bf16.h>
#include <cstdint>

#define NEG_INF_F (-1.0e12f)

constexpr int S_  = 1024;
constexpr int D_  = 128;
constexpr int BH_ = 32;   // B*H

// Approx scores (bf16), candidate key indices, candidate counts.
static __device__ __align__(16) __nv_bfloat16 g_scores[(size_t)BH_ * S_ * S_];
static __device__ uint16_t g_pidx [(size_t)BH_ * S_ * S_];
static __device__ int      g_count[(size_t)BH_ * S_];

// ---------------------------------------------------------------------------
// PTX helpers
// ---------------------------------------------------------------------------
__device__ __forceinline__ void ldsm4(uint32_t* r, uint32_t addr) {
    asm volatile("ldmatrix.sync.aligned.m8n8.x4.shared.b16 {%0,%1,%2,%3}, [%4];\n"
                 : "=r"(r[0]), "=r"(r[1]), "=r"(r[2]), "=r"(r[3]) : "r"(addr));
}
__device__ __forceinline__ void mma_bf16(float* c, const uint32_t* a,
                                         uint32_t b0, uint32_t b1) {
    asm volatile("mma.sync.aligned.m16n8k16.row.col.f32.bf16.bf16.f32 "
                 "{%0,%1,%2,%3}, {%4,%5,%6,%7}, {%8,%9}, {%0,%1,%2,%3};\n"
                 : "+f"(c[0]), "+f"(c[1]), "+f"(c[2]), "+f"(c[3])
                 : "r"(a[0]), "r"(a[1]), "r"(a[2]), "r"(a[3]), "r"(b0), "r"(b1));
}
__device__ __forceinline__ uint32_t cvt2(float a, float b) {
    __nv_bfloat162 h = __floats2bfloat162_rn(a, b);
    return *(uint32_t*)&h;
}

// ---------------------------------------------------------------------------
// Kernel 1: approx scores (bf16) = mask ? scale * Q K^T : -1e12
// Single-plane bf16 MMA (support finding only; exact values recomputed later).
// 64x128 tile, 256 threads (2m x 4n warps, 32x32 warp tile), BK=32,
// double-buffered smem, distance-2 register pipeline, 2 CTAs/SM.
// ---------------------------------------------------------------------------
__global__ void __launch_bounds__(256, 2) qk_kernel(const float* __restrict__ q,
                                                    const float* __restrict__ k,
                                                    const int*   __restrict__ mask) {
    extern __shared__ __align__(16) uint8_t sm[];
    // per buffer: QH 64x40 bf16 (5120B), KH 128x40 bf16 (10240B)
    constexpr uint32_t QH = 0, KH = 5120, BUF = 15360;
    const uint32_t sb = (uint32_t)__cvta_generic_to_shared(sm);

    const int tid  = threadIdx.x;
    const int lane = tid & 31;
    const int wid  = tid >> 5;
    const int wm   = wid & 1;
    const int wn   = wid >> 1;
    const int bh   = blockIdx.z;
    const int b    = bh >> 3;
    const int row0 = blockIdx.x << 6;
    const int col0 = blockIdx.y << 7;

    const int pr = tid >> 3;
    const int pc = (tid & 7) << 2;
    const float* qp0 = q + ((size_t)bh * S_ + row0 + pr) * D_ + pc;
    const float* qp1 = qp0 + (size_t)32 * D_;
    const float* kp  = k + ((size_t)bh * S_ + col0 + pr) * D_ + pc;

    float4 Qr[2][2], Kr[2][4];

    auto load_chunk = [&](int c, int s) {
        Qr[s][0] = *(const float4*)(qp0 + c * 32);
        Qr[s][1] = *(const float4*)(qp1 + c * 32);
        #pragma unroll
        for (int i = 0; i < 4; ++i)
            Kr[s][i] = *(const float4*)(kp + (size_t)(32 * i) * D_ + c * 32);
    };
    auto store_chunk = [&](int s, int buf) {
        uint8_t* B = sm + (uint32_t)buf * BUF;
        #pragma unroll
        for (int i = 0; i < 2; ++i) {
            float4 vq = Qr[s][i];
            uint32_t off = 2u * ((uint32_t)(pr + 32 * i) * 40 + pc);
            *(uint2*)(B + QH + off) = make_uint2(cvt2(vq.x, vq.y), cvt2(vq.z, vq.w));
        }
        #pragma unroll
        for (int i = 0; i < 4; ++i) {
            float4 vk = Kr[s][i];
            uint32_t off = 2u * ((uint32_t)(pr + 32 * i) * 40 + pc);
            *(uint2*)(B + KH + off) = make_uint2(cvt2(vk.x, vk.y), cvt2(vk.z, vk.w));
        }
    };

    const int lrA = lane & 15, lcA = (lane >> 4) << 3;
    const int lrB = ((lane >> 4) << 3) + (lane & 7), lcB = ((lane >> 3) & 1) << 3;
    uint32_t aAddr[2], bAddr[2];
    #pragma unroll
    for (int mi = 0; mi < 2; ++mi)
        aAddr[mi] = sb + QH + 2u * ((uint32_t)(wm * 32 + mi * 16 + lrA) * 40 + lcA);
    #pragma unroll
    for (int nt = 0; nt < 2; ++nt)
        bAddr[nt] = sb + KH + 2u * ((uint32_t)(wn * 32 + nt * 16 + lrB) * 40 + lcB);

    load_chunk(0, 0);
    store_chunk(0, 0);
    load_chunk(1, 1);
    __syncthreads();

    float acc[2][4][4] = {};
    constexpr int NC = D_ / 32;

    #pragma unroll
    for (int c = 0; c < NC; ++c) {
        const int buf = c & 1;
        if (c + 2 < NC) load_chunk(c + 2, buf);

        const uint32_t bo = (uint32_t)buf * BUF;
        #pragma unroll
        for (int kk = 0; kk < 2; ++kk) {
            const uint32_t ko = 32u * kk;
            uint32_t Ah[2][4], Bh[2][4];
            ldsm4(Ah[0], aAddr[0] + bo + ko);
            ldsm4(Ah[1], aAddr[1] + bo + ko);
            ldsm4(Bh[0], bAddr[0] + bo + ko);
            ldsm4(Bh[1], bAddr[1] + bo + ko);
            #pragma unroll
            for (int mi = 0; mi < 2; ++mi)
                #pragma unroll
                for (int ni = 0; ni < 4; ++ni)
                    mma_bf16(acc[mi][ni], Ah[mi],
                             Bh[ni >> 1][(ni & 1) * 2], Bh[ni >> 1][(ni & 1) * 2 + 1]);
        }

        if (c + 1 < NC) store_chunk((c + 1) & 1, (c + 1) & 1);
        __syncthreads();
    }

    const float scale = 0.08838834764831845f;
    __nv_bfloat16* srow = g_scores + (size_t)bh * S_ * S_;
    const int*     mrow = mask     + (size_t)b  * S_ * S_;
    const int      rb   = row0 + wm * 32 + (lane >> 2);
    const int      cb   = col0 + wn * 32 + ((lane & 3) << 1);

    #pragma unroll
    for (int mi = 0; mi < 2; ++mi)
        #pragma unroll
        for (int h = 0; h < 2; ++h) {
            int r = rb + mi * 16 + h * 8;
            #pragma unroll
            for (int ni = 0; ni < 4; ++ni) {
                int cc = cb + ni * 8;
                int2 mk = *(const int2*)(mrow + (size_t)r * S_ + cc);
                float f0 = mk.x ? acc[mi][ni][2 * h]     * scale : NEG_INF_F;
                float f1 = mk.y ? acc[mi][ni][2 * h + 1] * scale : NEG_INF_F;
                *(__nv_bfloat162*)(srow + (size_t)r * S_ + cc) =
                    __floats2bfloat162_rn(f0, f1);
            }
        }
}

// ---------------------------------------------------------------------------
// Kernel 2: approx entmax-1.5 tau + CANDIDATE selection, one warp per row.
// Newton on bf16 scores; emits all key indices with x > tau - 0.1 (margin
// provably covers the exact support given bf16 score error << 0.1).
// ---------------------------------------------------------------------------
__global__ void __launch_bounds__(512) entmax_kernel() {
    const int tid  = threadIdx.x;
    const int lane = tid & 31;
    const int wid  = tid >> 5;
    const size_t row = (size_t)blockIdx.x * 16 + wid;

    const uint4* rowp = (const uint4*)(g_scores + row * S_);   // 128 uint4

    float x[32];
    float m = -3.4e38f;
    #pragma unroll
    for (int j = 0; j < 4; ++j) {
        uint4 w = rowp[(j << 5) + lane];                        // 8 bf16, coalesced
        float2 f0 = __bfloat1622float2(*(__nv_bfloat162*)&w.x);
        float2 f1 = __bfloat1622float2(*(__nv_bfloat162*)&w.y);
        float2 f2 = __bfloat1622float2(*(__nv_bfloat162*)&w.z);
        float2 f3 = __bfloat1622float2(*(__nv_bfloat162*)&w.w);
        x[j*8+0] = f0.x; x[j*8+1] = f0.y; x[j*8+2] = f1.x; x[j*8+3] = f1.y;
        x[j*8+4] = f2.x; x[j*8+5] = f2.y; x[j*8+6] = f3.x; x[j*8+7] = f3.y;
        #pragma unroll
        for (int e = 0; e < 8; ++e) m = fmaxf(m, x[j*8+e]);
    }
    #pragma unroll
    for (int o = 16; o; o >>= 1) m = fmaxf(m, __shfl_xor_sync(0xffffffffu, m, o));

    #pragma unroll
    for (int e = 0; e < 32; ++e) x[e] = (x[e] - m) * 0.5f;

    float tau = -1.0f;
    for (int it = 0; it < 16; ++it) {
        float s1 = 0.0f, s2 = 0.0f;
        #pragma unroll
        for (int e = 0; e < 32; ++e) {
            float t = fmaxf(x[e] - tau, 0.0f);
            s1 += t;
            s2 = fmaf(t, t, s2);
        }
        #pragma unroll
        for (int o = 16; o; o >>= 1) {
            s1 += __shfl_xor_sync(0xffffffffu, s1, o);
            s2 += __shfl_xor_sync(0xffffffffu, s2, o);
        }
        tau += (s2 - 1.0f) / (2.0f * s1);
        tau  = fminf(tau, -0.03125f);
        if (fabsf(s2 - 1.0f) < 1e-4f) break;     // approx tau is enough
    }

    // candidate selection with margin
    const float thr = tau - 0.1f;
    uint16_t* pi = g_pidx + row * (size_t)S_;
    int base = 0;
    #pragma unroll
    for (int j = 0; j < 4; ++j)
        #pragma unroll
        for (int e = 0; e < 8; ++e) {
            bool sel = x[j*8+e] > thr;
            unsigned bm = __ballot_sync(0xffffffffu, sel);
            if (sel) {
                int pos = base + __popc(bm & ((1u << lane) - 1u));
                pi[pos] = (uint16_t)(((j << 5) + lane) * 8 + e);
            }
            base += __popc(bm);
        }
    if (lane == 0) g_count[row] = base;
}

// ---------------------------------------------------------------------------
// Kernel 3: exact refine + sparse PV. One warp per row (8 rows/CTA):
//  1) exact fp32 q.k for each candidate (candidates over lanes, q in smem)
//  2) exact rowmax over candidates (true argmax is always a candidate)
//  3) exact Newton for tau over candidates (== full-row solution: all
//     non-candidates are provably below tau)
//  4) p = (x - tau)+^2, gather V, fp32 accumulate. Fully exact fp32.
// ---------------------------------------------------------------------------
__global__ void __launch_bounds__(256) refine_pv_kernel(const float* __restrict__ q,
                                                        const float* __restrict__ k,
                                                        const float* __restrict__ v,
                                                        float* __restrict__ out) {
    __shared__ float qs[8][128];
    __shared__ float xs[8][1024];

    const int lane = threadIdx.x & 31;
    const int wid  = threadIdx.x >> 5;
    const size_t row = (size_t)blockIdx.x * 8 + wid;
    const int bh = (int)(row >> 10);
    const float scale = 0.08838834764831845f;

    // q row -> smem
    float4 qv = ((const float4*)(q + row * D_))[lane];
    *(float4*)&qs[wid][lane << 2] = qv;
    __syncwarp();

    const int cnt = g_count[row];
    const uint16_t* pi = g_pidx + row * (size_t)S_;

    // 1) exact scores for candidates
    const float4* q4 = (const float4*)qs[wid];
    for (int c = lane; c < cnt; c += 32) {
        int ki = pi[c];
        const float4* kr = (const float4*)(k + ((size_t)bh * S_ + ki) * D_);
        float s = 0.0f;
        #pragma unroll
        for (int d = 0; d < 32; ++d) {
            float4 kv = kr[d], qq = q4[d];
            s = fmaf(qq.x, kv.x, s); s = fmaf(qq.y, kv.y, s);
            s = fmaf(qq.z, kv.z, s); s = fmaf(qq.w, kv.w, s);
        }
        xs[wid][c] = s * scale;
    }
    __syncwarp();

    // 2) exact rowmax over candidates
    float m = -3.4e38f;
    for (int c = lane; c < cnt; c += 32) m = fmaxf(m, xs[wid][c]);
    #pragma unroll
    for (int o = 16; o; o >>= 1) m = fmaxf(m, __shfl_xor_sync(0xffffffffu, m, o));
    for (int c = lane; c < cnt; c += 32) xs[wid][c] = (xs[wid][c] - m) * 0.5f;
    __syncwarp();

    // 3) exact Newton
    float tau = -1.0f;
    for (int it = 0; it < 20; ++it) {
        float s1 = 0.0f, s2 = 0.0f;
        for (int c = lane; c < cnt; c += 32) {
            float t = fmaxf(xs[wid][c] - tau, 0.0f);
            s1 += t;
            s2 = fmaf(t, t, s2);
        }
        #pragma unroll
        for (int o = 16; o; o >>= 1) {
            s1 += __shfl_xor_sync(0xffffffffu, s1, o);
            s2 += __shfl_xor_sync(0xffffffffu, s2, o);
        }
        tau += (s2 - 1.0f) / (2.0f * s1);
        tau  = fminf(tau, -0.03125f);
        if (fabsf(s2 - 1.0f) < 2e-6f) break;
    }

    // 4) sparse PV, exact fp32
    const float* vg = v + (size_t)bh * S_ * D_ + (lane << 2);
    float4 acc = make_float4(0.f, 0.f, 0.f, 0.f);
    for (int c = 0; c < cnt; ++c) {
        float t = xs[wid][c] - tau;
        if (t > 0.0f) {
            float p = t * t;
            float4 vv = *(const float4*)(vg + (size_t)pi[c] * D_);
            acc.x = fmaf(p, vv.x, acc.x); acc.y = fmaf(p, vv.y, acc.y);
            acc.z = fmaf(p, vv.z, acc.z); acc.w = fmaf(p, vv.w, acc.w);
        }
    }
    *(float4*)(out + row * D_ + (lane << 2)) = acc;
}

// ---------------------------------------------------------------------------
extern "C" void kernel_launch(void* const* d_in, const int* in_sizes, int n_in,
                              void* d_out, int out_size) {
    (void)in_sizes; (void)n_in; (void)out_size;
    const float* q    = (const float*)d_in[0];
    const float* k    = (const float*)d_in[1];
    const float* v    = (const float*)d_in[2];
    const int*   mask = (const int*)d_in[3];
    float*       out  = (float*)d_out;

    constexpr int QK_SMEM = 30720;   // 2 buffers of 15360B
    cudaFuncSetAttribute(qk_kernel, cudaFuncAttributeMaxDynamicSharedMemorySize, QK_SMEM);

    qk_kernel<<<dim3(16, 8, BH_), 256, QK_SMEM>>>(q, k, mask);
    entmax_kernel<<<BH_ * S_ / 16, 512>>>();
    refine_pv_kernel<<<BH_ * S_ / 8, 256>>>(q, k, v, out);
}

// round 12
// speedup vs baseline: 1.8142x; 1.8142x over previous
#include <cuda_runtime.h>
#include <cuda_bf16.h>
#include <cstdint>

#define NEG_INF_F (-1.0e12f)

constexpr int S_  = 1024;
constexpr int D_  = 128;
constexpr int BH_ = 32;   // B*H

// Approx scores (bf16), candidate indices/counts, approx (rowmax, tau).
static __device__ __align__(16) __nv_bfloat16 g_scores[(size_t)BH_ * S_ * S_];
static __device__ uint16_t g_pidx [(size_t)BH_ * S_ * S_];
static __device__ int      g_count[(size_t)BH_ * S_];
static __device__ float2   g_mt   [(size_t)BH_ * S_];

// ---------------------------------------------------------------------------
// PTX helpers
// ---------------------------------------------------------------------------
__device__ __forceinline__ void ldsm4(uint32_t* r, uint32_t addr) {
    asm volatile("ldmatrix.sync.aligned.m8n8.x4.shared.b16 {%0,%1,%2,%3}, [%4];\n"
                 : "=r"(r[0]), "=r"(r[1]), "=r"(r[2]), "=r"(r[3]) : "r"(addr));
}
__device__ __forceinline__ void mma_bf16(float* c, const uint32_t* a,
                                         uint32_t b0, uint32_t b1) {
    asm volatile("mma.sync.aligned.m16n8k16.row.col.f32.bf16.bf16.f32 "
                 "{%0,%1,%2,%3}, {%4,%5,%6,%7}, {%8,%9}, {%0,%1,%2,%3};\n"
                 : "+f"(c[0]), "+f"(c[1]), "+f"(c[2]), "+f"(c[3])
                 : "r"(a[0]), "r"(a[1]), "r"(a[2]), "r"(a[3]), "r"(b0), "r"(b1));
}
__device__ __forceinline__ uint32_t cvt2(float a, float b) {
    __nv_bfloat162 h = __floats2bfloat162_rn(a, b);
    return *(uint32_t*)&h;
}

// ---------------------------------------------------------------------------
// Kernel 1: approx scores (bf16) = mask ? scale * Q K^T : -1e12
// (unchanged from round 11: 64x128 tile, single-plane bf16 MMA, 2 CTAs/SM)
// ---------------------------------------------------------------------------
__global__ void __launch_bounds__(256, 2) qk_kernel(const float* __restrict__ q,
                                                    const float* __restrict__ k,
                                                    const int*   __restrict__ mask) {
    extern __shared__ __align__(16) uint8_t sm[];
    constexpr uint32_t QH = 0, KH = 5120, BUF = 15360;
    const uint32_t sb = (uint32_t)__cvta_generic_to_shared(sm);

    const int tid  = threadIdx.x;
    const int lane = tid & 31;
    const int wid  = tid >> 5;
    const int wm   = wid & 1;
    const int wn   = wid >> 1;
    const int bh   = blockIdx.z;
    const int b    = bh >> 3;
    const int row0 = blockIdx.x << 6;
    const int col0 = blockIdx.y << 7;

    const int pr = tid >> 3;
    const int pc = (tid & 7) << 2;
    const float* qp0 = q + ((size_t)bh * S_ + row0 + pr) * D_ + pc;
    const float* qp1 = qp0 + (size_t)32 * D_;
    const float* kp  = k + ((size_t)bh * S_ + col0 + pr) * D_ + pc;

    float4 Qr[2][2], Kr[2][4];

    auto load_chunk = [&](int c, int s) {
        Qr[s][0] = *(const float4*)(qp0 + c * 32);
        Qr[s][1] = *(const float4*)(qp1 + c * 32);
        #pragma unroll
        for (int i = 0; i < 4; ++i)
            Kr[s][i] = *(const float4*)(kp + (size_t)(32 * i) * D_ + c * 32);
    };
    auto store_chunk = [&](int s, int buf) {
        uint8_t* B = sm + (uint32_t)buf * BUF;
        #pragma unroll
        for (int i = 0; i < 2; ++i) {
            float4 vq = Qr[s][i];
            uint32_t off = 2u * ((uint32_t)(pr + 32 * i) * 40 + pc);
            *(uint2*)(B + QH + off) = make_uint2(cvt2(vq.x, vq.y), cvt2(vq.z, vq.w));
        }
        #pragma unroll
        for (int i = 0; i < 4; ++i) {
            float4 vk = Kr[s][i];
            uint32_t off = 2u * ((uint32_t)(pr + 32 * i) * 40 + pc);
            *(uint2*)(B + KH + off) = make_uint2(cvt2(vk.x, vk.y), cvt2(vk.z, vk.w));
        }
    };

    const int lrA = lane & 15, lcA = (lane >> 4) << 3;
    const int lrB = ((lane >> 4) << 3) + (lane & 7), lcB = ((lane >> 3) & 1) << 3;
    uint32_t aAddr[2], bAddr[2];
    #pragma unroll
    for (int mi = 0; mi < 2; ++mi)
        aAddr[mi] = sb + QH + 2u * ((uint32_t)(wm * 32 + mi * 16 + lrA) * 40 + lcA);
    #pragma unroll
    for (int nt = 0; nt < 2; ++nt)
        bAddr[nt] = sb + KH + 2u * ((uint32_t)(wn * 32 + nt * 16 + lrB) * 40 + lcB);

    load_chunk(0, 0);
    store_chunk(0, 0);
    load_chunk(1, 1);
    __syncthreads();

    float acc[2][4][4] = {};
    constexpr int NC = D_ / 32;

    #pragma unroll
    for (int c = 0; c < NC; ++c) {
        const int buf = c & 1;
        if (c + 2 < NC) load_chunk(c + 2, buf);

        const uint32_t bo = (uint32_t)buf * BUF;
        #pragma unroll
        for (int kk = 0; kk < 2; ++kk) {
            const uint32_t ko = 32u * kk;
            uint32_t Ah[2][4], Bh[2][4];
            ldsm4(Ah[0], aAddr[0] + bo + ko);
            ldsm4(Ah[1], aAddr[1] + bo + ko);
            ldsm4(Bh[0], bAddr[0] + bo + ko);
            ldsm4(Bh[1], bAddr[1] + bo + ko);
            #pragma unroll
            for (int mi = 0; mi < 2; ++mi)
                #pragma unroll
                for (int ni = 0; ni < 4; ++ni)
                    mma_bf16(acc[mi][ni], Ah[mi],
                             Bh[ni >> 1][(ni & 1) * 2], Bh[ni >> 1][(ni & 1) * 2 + 1]);
        }

        if (c + 1 < NC) store_chunk((c + 1) & 1, (c + 1) & 1);
        __syncthreads();
    }

    const float scale = 0.08838834764831845f;
    __nv_bfloat16* srow = g_scores + (size_t)bh * S_ * S_;
    const int*     mrow = mask     + (size_t)b  * S_ * S_;
    const int      rb   = row0 + wm * 32 + (lane >> 2);
    const int      cb   = col0 + wn * 32 + ((lane & 3) << 1);

    #pragma unroll
    for (int mi = 0; mi < 2; ++mi)
        #pragma unroll
        for (int h = 0; h < 2; ++h) {
            int r = rb + mi * 16 + h * 8;
            #pragma unroll
            for (int ni = 0; ni < 4; ++ni) {
                int cc = cb + ni * 8;
                int2 mk = *(const int2*)(mrow + (size_t)r * S_ + cc);
                float f0 = mk.x ? acc[mi][ni][2 * h]     * scale : NEG_INF_F;
                float f1 = mk.y ? acc[mi][ni][2 * h + 1] * scale : NEG_INF_F;
                *(__nv_bfloat162*)(srow + (size_t)r * S_ + cc) =
                    __floats2bfloat162_rn(f0, f1);
            }
        }
}

// ---------------------------------------------------------------------------
// Kernel 2: approx entmax tau + candidate selection (margin 0.1), warp/row.
// Also stores (approx rowmax, approx tau) for the exact Newton warm start.
// ---------------------------------------------------------------------------
__global__ void __launch_bounds__(512) entmax_kernel() {
    const int tid  = threadIdx.x;
    const int lane = tid & 31;
    const int wid  = tid >> 5;
    const size_t row = (size_t)blockIdx.x * 16 + wid;

    const uint4* rowp = (const uint4*)(g_scores + row * S_);

    float x[32];
    float m = -3.4e38f;
    #pragma unroll
    for (int j = 0; j < 4; ++j) {
        uint4 w = rowp[(j << 5) + lane];
        float2 f0 = __bfloat1622float2(*(__nv_bfloat162*)&w.x);
        float2 f1 = __bfloat1622float2(*(__nv_bfloat162*)&w.y);
        float2 f2 = __bfloat1622float2(*(__nv_bfloat162*)&w.z);
        float2 f3 = __bfloat1622float2(*(__nv_bfloat162*)&w.w);
        x[j*8+0] = f0.x; x[j*8+1] = f0.y; x[j*8+2] = f1.x; x[j*8+3] = f1.y;
        x[j*8+4] = f2.x; x[j*8+5] = f2.y; x[j*8+6] = f3.x; x[j*8+7] = f3.y;
        #pragma unroll
        for (int e = 0; e < 8; ++e) m = fmaxf(m, x[j*8+e]);
    }
    #pragma unroll
    for (int o = 16; o; o >>= 1) m = fmaxf(m, __shfl_xor_sync(0xffffffffu, m, o));

    #pragma unroll
    for (int e = 0; e < 32; ++e) x[e] = (x[e] - m) * 0.5f;

    float tau = -1.0f;
    for (int it = 0; it < 16; ++it) {
        float s1 = 0.0f, s2 = 0.0f;
        #pragma unroll
        for (int e = 0; e < 32; ++e) {
            float t = fmaxf(x[e] - tau, 0.0f);
            s1 += t;
            s2 = fmaf(t, t, s2);
        }
        #pragma unroll
        for (int o = 16; o; o >>= 1) {
            s1 += __shfl_xor_sync(0xffffffffu, s1, o);
            s2 += __shfl_xor_sync(0xffffffffu, s2, o);
        }
        tau += (s2 - 1.0f) / (2.0f * s1);
        tau  = fminf(tau, -0.03125f);
        if (fabsf(s2 - 1.0f) < 1e-4f) break;
    }

    const float thr = tau - 0.1f;
    uint16_t* pi = g_pidx + row * (size_t)S_;
    int base = 0;
    #pragma unroll
    for (int j = 0; j < 4; ++j)
        #pragma unroll
        for (int e = 0; e < 8; ++e) {
            bool sel = x[j*8+e] > thr;
            unsigned bm = __ballot_sync(0xffffffffu, sel);
            if (sel) {
                int pos = base + __popc(bm & ((1u << lane) - 1u));
                pi[pos] = (uint16_t)(((j << 5) + lane) * 8 + e);
            }
            base += __popc(bm);
        }
    if (lane == 0) {
        g_count[row] = base;
        g_mt[row]    = make_float2(m, tau);
    }
}

// ---------------------------------------------------------------------------
// Kernel 3: exact refine + sparse PV, one warp per row.
// Candidate dots: 8 lanes per candidate, 4 candidates in flight -> each K-row
// read is 4 contiguous 128B segments per warp instruction (coalesced), vs 32
// scattered lines before. Exact fp32 throughout; Newton warm-started from the
// approx (m, tau), provably from below (0.05 safety >> 0.01 score error).
// ---------------------------------------------------------------------------
__global__ void __launch_bounds__(256) refine_pv_kernel(const float* __restrict__ q,
                                                        const float* __restrict__ k,
                                                        const float* __restrict__ v,
                                                        const int*   __restrict__ mask,
                                                        float* __restrict__ out) {
    __shared__ float xs[8][1024];

    const int lane = threadIdx.x & 31;
    const int wid  = threadIdx.x >> 5;
    const size_t row = (size_t)blockIdx.x * 8 + wid;
    const int bh = (int)(row >> 10);
    const int b  = bh >> 3;
    const float scale = 0.08838834764831845f;

    const int sub = lane & 7;     // lane within candidate group
    const int grp = lane >> 3;    // candidate group 0..3

    // q chunks for this lane's dims: float4 indices sub, sub+8, sub+16, sub+24
    const float4* q4 = (const float4*)(q + row * D_);
    float4 qreg[4];
    #pragma unroll
    for (int r = 0; r < 4; ++r) qreg[r] = q4[sub + 8 * r];

    const int cnt = g_count[row];
    const uint16_t* pi = g_pidx + row * (size_t)S_;
    const float2 mt = g_mt[row];
    const float4* kb = (const float4*)(k + (size_t)bh * S_ * D_);
    const int* mrow = mask + ((size_t)b * S_ + (row & 1023)) * S_;

    // 1) exact scores: 4 candidates per pass, 8 lanes each
    for (int cg = 0; cg < cnt; cg += 4) {
        int c = cg + grp;
        int cc = (c < cnt) ? c : (cnt - 1);
        int ki = pi[cc];
        float s = 0.0f;
        #pragma unroll
        for (int r = 0; r < 4; ++r) {
            float4 kv = kb[(size_t)ki * 32 + sub + 8 * r];
            s = fmaf(qreg[r].x, kv.x, s);
            s = fmaf(qreg[r].y, kv.y, s);
            s = fmaf(qreg[r].z, kv.z, s);
            s = fmaf(qreg[r].w, kv.w, s);
        }
        #pragma unroll
        for (int o = 4; o; o >>= 1) s += __shfl_xor_sync(0xffffffffu, s, o);
        if (c < cnt && sub == 0)
            xs[wid][c] = mrow[ki] ? s * scale : NEG_INF_F;
    }
    __syncwarp();

    // 2) exact rowmax over candidates (true argmax is always a candidate)
    float m = -3.4e38f;
    for (int c = lane; c < cnt; c += 32) m = fmaxf(m, xs[wid][c]);
    #pragma unroll
    for (int o = 16; o; o >>= 1) m = fmaxf(m, __shfl_xor_sync(0xffffffffu, m, o));
    for (int c = lane; c < cnt; c += 32) xs[wid][c] = (xs[wid][c] - m) * 0.5f;
    __syncwarp();

    // 3) exact Newton, warm-started below the root
    float tau = fminf(mt.y + (mt.x - m) * 0.5f - 0.05f, -0.03125f);
    for (int it = 0; it < 12; ++it) {
        float s1 = 0.0f, s2 = 0.0f;
        for (int c = lane; c < cnt; c += 32) {
            float t = fmaxf(xs[wid][c] - tau, 0.0f);
            s1 += t;
            s2 = fmaf(t, t, s2);
        }
        #pragma unroll
        for (int o = 16; o; o >>= 1) {
            s1 += __shfl_xor_sync(0xffffffffu, s1, o);
            s2 += __shfl_xor_sync(0xffffffffu, s2, o);
        }
        tau += (s2 - 1.0f) / (2.0f * s1);
        tau  = fminf(tau, -0.03125f);
        if (fabsf(s2 - 1.0f) < 2e-6f) break;
    }

    // 4) sparse PV: lane owns dims [lane*4, lane*4+4), V reads coalesced
    const float* vg = v + (size_t)bh * S_ * D_ + (lane << 2);
    float4 acc = make_float4(0.f, 0.f, 0.f, 0.f);
    for (int c = 0; c < cnt; ++c) {
        float t = xs[wid][c] - tau;
        if (t > 0.0f) {
            float p = t * t;
            float4 vv = *(const float4*)(vg + (size_t)pi[c] * D_);
            acc.x = fmaf(p, vv.x, acc.x); acc.y = fmaf(p, vv.y, acc.y);
            acc.z = fmaf(p, vv.z, acc.z); acc.w = fmaf(p, vv.w, acc.w);
        }
    }
    *(float4*)(out + row * D_ + (lane << 2)) = acc;
}

// ---------------------------------------------------------------------------
extern "C" void kernel_launch(void* const* d_in, const int* in_sizes, int n_in,
                              void* d_out, int out_size) {
    (void)in_sizes; (void)n_in; (void)out_size;
    const float* q    = (const float*)d_in[0];
    const float* k    = (const float*)d_in[1];
    const float* v    = (const float*)d_in[2];
    const int*   mask = (const int*)d_in[3];
    float*       out  = (float*)d_out;

    constexpr int QK_SMEM = 30720;
    cudaFuncSetAttribute(qk_kernel, cudaFuncAttributeMaxDynamicSharedMemorySize, QK_SMEM);

    qk_kernel<<<dim3(16, 8, BH_), 256, QK_SMEM>>>(q, k, mask);
    entmax_kernel<<<BH_ * S_ / 16, 512>>>();
    refine_pv_kernel<<<BH_ * S_ / 8, 256>>>(q, k, v, mask, out);
}

// round 13
// speedup vs baseline: 1.9814x; 1.0922x over previous
#include <cuda_runtime.h>
#include <cuda_bf16.h>
#include <cstdint>

#define NEG_INF_F (-1.0e12f)

constexpr int S_  = 1024;
constexpr int D_  = 128;
constexpr int BH_ = 32;   // B*H

// Candidate indices / counts / approx (rowmax, tau) — scores never hit DRAM.
static __device__ uint16_t g_pidx [(size_t)BH_ * S_ * S_];
static __device__ int      g_count[(size_t)BH_ * S_];
static __device__ float2   g_mt   [(size_t)BH_ * S_];

// ---------------------------------------------------------------------------
// PTX helpers
// ---------------------------------------------------------------------------
__device__ __forceinline__ void ldsm4(uint32_t* r, uint32_t addr) {
    asm volatile("ldmatrix.sync.aligned.m8n8.x4.shared.b16 {%0,%1,%2,%3}, [%4];\n"
                 : "=r"(r[0]), "=r"(r[1]), "=r"(r[2]), "=r"(r[3]) : "r"(addr));
}
__device__ __forceinline__ void mma_bf16(float* c, const uint32_t* a,
                                         uint32_t b0, uint32_t b1) {
    asm volatile("mma.sync.aligned.m16n8k16.row.col.f32.bf16.bf16.f32 "
                 "{%0,%1,%2,%3}, {%4,%5,%6,%7}, {%8,%9}, {%0,%1,%2,%3};\n"
                 : "+f"(c[0]), "+f"(c[1]), "+f"(c[2]), "+f"(c[3])
                 : "r"(a[0]), "r"(a[1]), "r"(a[2]), "r"(a[3]), "r"(b0), "r"(b1));
}
__device__ __forceinline__ uint32_t cvt2(float a, float b) {
    __nv_bfloat162 h = __floats2bfloat162_rn(a, b);
    return *(uint32_t*)&h;
}

// ---------------------------------------------------------------------------
// Kernel 1 (FUSED): approx scores (bf16, smem-resident) + entmax tau +
// candidate selection. One CTA = 64 query rows x ALL 1024 keys.
//   smem: sQ [64][136] bf16 (17408B) | sK [256][136] bf16 (69632B)
//         sS [64][1032] bf16 (132096B, pitch 2064B kills STS bank conflicts)
//   Phase A: 4 key-blocks of 256; load K block -> MMA (16 warps, 2m x 8n,
//            warp tile 32x32) -> masked epilogue into sS.
//   Phase B: warp-per-row Newton on smem scores; margin-0.1 candidates ->
//            g_pidx/g_count/g_mt. The 134MB score round-trip is GONE.
// ---------------------------------------------------------------------------
__global__ void __launch_bounds__(512) fused_qk_select_kernel(
        const float* __restrict__ q, const float* __restrict__ k,
        const int* __restrict__ mask) {
    extern __shared__ __align__(16) uint8_t sm[];
    constexpr uint32_t SQ = 0, SK = 17408, SS = 87040;   // byte offsets
    const uint32_t sb = (uint32_t)__cvta_generic_to_shared(sm);

    const int tid  = threadIdx.x;
    const int lane = tid & 31;
    const int wid  = tid >> 5;
    const int wm   = wid & 1;          // 2 m-slabs of 32
    const int wn   = wid >> 1;         // 8 n-slabs of 32
    const int bh   = blockIdx.y;
    const int b    = bh >> 3;
    const int row0 = blockIdx.x << 6;  // 64 query rows

    // ---- load Q (64x128 fp32 -> bf16, pitch 136)
    const int gr  = tid >> 3;          // 0..63
    const int gs8 = tid & 7;           // segment
    {
        const float* qg = q + ((size_t)bh * S_ + row0 + gr) * D_;
        #pragma unroll
        for (int i = 0; i < 4; ++i) {
            int c4 = (gs8 + 8 * i) << 2;
            float4 v = *(const float4*)(qg + c4);
            *(uint2*)(sm + SQ + 2u * ((uint32_t)gr * 136 + c4)) =
                make_uint2(cvt2(v.x, v.y), cvt2(v.z, v.w));
        }
    }

    // ---- ldmatrix addresses
    const int lrA = lane & 15, lcA = (lane >> 4) << 3;
    const int lrB = ((lane >> 4) << 3) + (lane & 7), lcB = ((lane >> 3) & 1) << 3;
    uint32_t aAddr[2], bAddr[2];
    #pragma unroll
    for (int mi = 0; mi < 2; ++mi)
        aAddr[mi] = sb + SQ + 2u * ((uint32_t)(wm * 32 + mi * 16 + lrA) * 136 + lcA);
    #pragma unroll
    for (int nt = 0; nt < 2; ++nt)
        bAddr[nt] = sb + SK + 2u * ((uint32_t)(wn * 32 + nt * 16 + lrB) * 136 + lcB);

    const float scale = 0.08838834764831845f;   // 1/sqrt(128)

    // ---- Phase A: 4 key blocks of 256
    for (int kb = 0; kb < 4; ++kb) {
        __syncthreads();   // prev block's ldsm/epilogue done; sK reusable; Q visible
        {
            const float* kg = k + ((size_t)bh * S_ + kb * 256) * D_;
            #pragma unroll
            for (int i = 0; i < 4; ++i) {
                int rr = gr + 64 * i;
                const float* kgr = kg + (size_t)rr * D_;
                #pragma unroll
                for (int jj = 0; jj < 4; ++jj) {
                    int c4 = (gs8 + 8 * jj) << 2;
                    float4 v = *(const float4*)(kgr + c4);
                    *(uint2*)(sm + SK + 2u * ((uint32_t)rr * 136 + c4)) =
                        make_uint2(cvt2(v.x, v.y), cvt2(v.z, v.w));
                }
            }
        }
        __syncthreads();

        float acc[2][4][4] = {};
        #pragma unroll
        for (int kk = 0; kk < 8; ++kk) {
            const uint32_t ko = 32u * kk;
            uint32_t A[2][4], Bf[2][4];
            ldsm4(A[0], aAddr[0] + ko);
            ldsm4(A[1], aAddr[1] + ko);
            ldsm4(Bf[0], bAddr[0] + ko);
            ldsm4(Bf[1], bAddr[1] + ko);
            #pragma unroll
            for (int mi = 0; mi < 2; ++mi)
                #pragma unroll
                for (int ni = 0; ni < 4; ++ni)
                    mma_bf16(acc[mi][ni], A[mi],
                             Bf[ni >> 1][(ni & 1) * 2], Bf[ni >> 1][(ni & 1) * 2 + 1]);
        }

        // ---- masked epilogue -> sS (bf16x2 stores, pitch 2064B)
        const int lrb = wm * 32 + (lane >> 2);
        const int cbb = wn * 32 + ((lane & 3) << 1);
        #pragma unroll
        for (int mi = 0; mi < 2; ++mi)
            #pragma unroll
            for (int h = 0; h < 2; ++h) {
                int lr = lrb + mi * 16 + h * 8;
                const int* mrow = mask + ((size_t)b * S_ + row0 + lr) * S_ + kb * 256;
                #pragma unroll
                for (int ni = 0; ni < 4; ++ni) {
                    int cc = cbb + ni * 8;
                    int2 mk = *(const int2*)(mrow + cc);
                    float f0 = mk.x ? acc[mi][ni][2 * h]     * scale : NEG_INF_F;
                    float f1 = mk.y ? acc[mi][ni][2 * h + 1] * scale : NEG_INF_F;
                    *(uint32_t*)(sm + SS + (uint32_t)lr * 2064
                                 + ((uint32_t)(kb * 256 + cc) << 1)) = cvt2(f0, f1);
                }
            }
    }
    __syncthreads();

    // ---- Phase B: warp-per-row approx entmax + candidate selection (4 rows/warp)
    for (int i = 0; i < 4; ++i) {
        const int lr = wid + 16 * i;
        const size_t row = ((size_t)bh << 10) + row0 + lr;

        float x[32];
        float m = -3.4e38f;
        #pragma unroll
        for (int j = 0; j < 4; ++j) {
            uint4 w = *(const uint4*)(sm + SS + (uint32_t)lr * 2064
                                      + (((j << 5) + lane) << 4));
            float2 f0 = __bfloat1622float2(*(__nv_bfloat162*)&w.x);
            float2 f1 = __bfloat1622float2(*(__nv_bfloat162*)&w.y);
            float2 f2 = __bfloat1622float2(*(__nv_bfloat162*)&w.z);
            float2 f3 = __bfloat1622float2(*(__nv_bfloat162*)&w.w);
            x[j*8+0] = f0.x; x[j*8+1] = f0.y; x[j*8+2] = f1.x; x[j*8+3] = f1.y;
            x[j*8+4] = f2.x; x[j*8+5] = f2.y; x[j*8+6] = f3.x; x[j*8+7] = f3.y;
            #pragma unroll
            for (int e = 0; e < 8; ++e) m = fmaxf(m, x[j*8+e]);
        }
        #pragma unroll
        for (int o = 16; o; o >>= 1) m = fmaxf(m, __shfl_xor_sync(0xffffffffu, m, o));

        #pragma unroll
        for (int e = 0; e < 32; ++e) x[e] = (x[e] - m) * 0.5f;

        float tau = -1.0f;
        for (int it = 0; it < 16; ++it) {
            float s1 = 0.0f, s2 = 0.0f;
            #pragma unroll
            for (int e = 0; e < 32; ++e) {
                float t = fmaxf(x[e] - tau, 0.0f);
                s1 += t;
                s2 = fmaf(t, t, s2);
            }
            #pragma unroll
            for (int o = 16; o; o >>= 1) {
                s1 += __shfl_xor_sync(0xffffffffu, s1, o);
                s2 += __shfl_xor_sync(0xffffffffu, s2, o);
            }
            tau += (s2 - 1.0f) / (2.0f * s1);
            tau  = fminf(tau, -0.03125f);
            if (fabsf(s2 - 1.0f) < 1e-4f) break;
        }

        const float thr = tau - 0.1f;    // margin >> bf16 score error
        uint16_t* pi = g_pidx + (row << 10);
        int base = 0;
        #pragma unroll
        for (int j = 0; j < 4; ++j)
            #pragma unroll
            for (int e = 0; e < 8; ++e) {
                bool sel = x[j*8+e] > thr;
                unsigned bm = __ballot_sync(0xffffffffu, sel);
                if (sel) {
                    int pos = base + __popc(bm & ((1u << lane) - 1u));
                    pi[pos] = (uint16_t)((((j << 5) + lane) << 3) + e);
                }
                base += __popc(bm);
            }
        if (lane == 0) {
            g_count[row] = base;
            g_mt[row]    = make_float2(m, tau);
        }
    }
}

// ---------------------------------------------------------------------------
// Kernel 2: exact refine + sparse PV, one warp per row (as round 12), plus
// candidate indices staged in smem to break the pi->K dependent-load chain.
// ---------------------------------------------------------------------------
__global__ void __launch_bounds__(256) refine_pv_kernel(const float* __restrict__ q,
                                                        const float* __restrict__ k,
                                                        const float* __restrict__ v,
                                                        const int*   __restrict__ mask,
                                                        float* __restrict__ out) {
    __shared__ float    xs  [8][1024];
    __shared__ uint16_t sidx[8][1024];

    const int lane = threadIdx.x & 31;
    const int wid  = threadIdx.x >> 5;
    const size_t row = (size_t)blockIdx.x * 8 + wid;
    const int bh = (int)(row >> 10);
    const int b  = bh >> 3;
    const float scale = 0.08838834764831845f;

    const int sub = lane & 7;     // lane within candidate group
    const int grp = lane >> 3;    // candidate group 0..3

    const float4* q4 = (const float4*)(q + row * D_);
    float4 qreg[4];
    #pragma unroll
    for (int r = 0; r < 4; ++r) qreg[r] = q4[sub + 8 * r];

    const int cnt = g_count[row];
    const uint16_t* pi = g_pidx + (row << 10);
    const float2 mt = g_mt[row];
    const float4* kb = (const float4*)(k + (size_t)bh * S_ * D_);
    const int* mrow = mask + ((size_t)b * S_ + (row & 1023)) * S_;

    // stage candidate indices in smem (coalesced, breaks dependent chains)
    for (int c = lane; c < cnt; c += 32) sidx[wid][c] = pi[c];
    __syncwarp();

    // 1) exact scores: 4 candidates per pass, 8 lanes each (coalesced K reads)
    for (int cg = 0; cg < cnt; cg += 4) {
        int c = cg + grp;
        int cc = (c < cnt) ? c : (cnt - 1);
        int ki = sidx[wid][cc];
        float s = 0.0f;
        #pragma unroll
        for (int r = 0; r < 4; ++r) {
            float4 kv = kb[(size_t)ki * 32 + sub + 8 * r];
            s = fmaf(qreg[r].x, kv.x, s);
            s = fmaf(qreg[r].y, kv.y, s);
            s = fmaf(qreg[r].z, kv.z, s);
            s = fmaf(qreg[r].w, kv.w, s);
        }
        #pragma unroll
        for (int o = 4; o; o >>= 1) s += __shfl_xor_sync(0xffffffffu, s, o);
        if (c < cnt && sub == 0)
            xs[wid][c] = mrow[ki] ? s * scale : NEG_INF_F;
    }
    __syncwarp();

    // 2) exact rowmax over candidates (true argmax is always a candidate)
    float m = -3.4e38f;
    for (int c = lane; c < cnt; c += 32) m = fmaxf(m, xs[wid][c]);
    #pragma unroll
    for (int o = 16; o; o >>= 1) m = fmaxf(m, __shfl_xor_sync(0xffffffffu, m, o));
    for (int c = lane; c < cnt; c += 32) xs[wid][c] = (xs[wid][c] - m) * 0.5f;
    __syncwarp();

    // 3) exact Newton, warm-started below the root
    float tau = fminf(mt.y + (mt.x - m) * 0.5f - 0.05f, -0.03125f);
    for (int it = 0; it < 12; ++it) {
        float s1 = 0.0f, s2 = 0.0f;
        for (int c = lane; c < cnt; c += 32) {
            float t = fmaxf(xs[wid][c] - tau, 0.0f);
            s1 += t;
            s2 = fmaf(t, t, s2);
        }
        #pragma unroll
        for (int o = 16; o; o >>= 1) {
            s1 += __shfl_xor_sync(0xffffffffu, s1, o);
            s2 += __shfl_xor_sync(0xffffffffu, s2, o);
        }
        tau += (s2 - 1.0f) / (2.0f * s1);
        tau  = fminf(tau, -0.03125f);
        if (fabsf(s2 - 1.0f) < 2e-6f) break;
    }

    // 4) sparse PV: lane owns dims [lane*4, lane*4+4), coalesced V reads
    const float* vg = v + (size_t)bh * S_ * D_ + (lane << 2);
    float4 acc = make_float4(0.f, 0.f, 0.f, 0.f);
    for (int c = 0; c < cnt; ++c) {
        float t = xs[wid][c] - tau;
        if (t > 0.0f) {
            float p = t * t;
            float4 vv = *(const float4*)(vg + (size_t)sidx[wid][c] * D_);
            acc.x = fmaf(p, vv.x, acc.x); acc.y = fmaf(p, vv.y, acc.y);
            acc.z = fmaf(p, vv.z, acc.z); acc.w = fmaf(p, vv.w, acc.w);
        }
    }
    *(float4*)(out + row * D_ + (lane << 2)) = acc;
}

// ---------------------------------------------------------------------------
extern "C" void kernel_launch(void* const* d_in, const int* in_sizes, int n_in,
                              void* d_out, int out_size) {
    (void)in_sizes; (void)n_in; (void)out_size;
    const float* q    = (const float*)d_in[0];
    const float* k    = (const float*)d_in[1];
    const float* v    = (const float*)d_in[2];
    const int*   mask = (const int*)d_in[3];
    float*       out  = (float*)d_out;

    constexpr int F_SMEM = 87040 + 64 * 2064;   // 219136 B
    cudaFuncSetAttribute(fused_qk_select_kernel,
                         cudaFuncAttributeMaxDynamicSharedMemorySize, F_SMEM);

    fused_qk_select_kernel<<<dim3(16, BH_), 512, F_SMEM>>>(q, k, mask);
    refine_pv_kernel<<<BH_ * S_ / 8, 256>>>(q, k, v, mask, out);
}